// round 13
// baseline (speedup 1.0000x reference)
#include <cuda_runtime.h>
#include <cuda_fp16.h>

#define VDIM 128
#define NB   8
#define SLAB 16384
#define VOL  2097152

// Scratch spectrum, half2, tiled layout:
//   idx(b,z,y,x) = b*VOL + (y*8 + x/16)*2048 + z*16 + (x%16)
// -> z-columns for fixed (y, x/16) are one contiguous 8 KB block (passB streams).
__device__ __half2 g_Z[(size_t)NB * VOL];

__device__ __forceinline__ size_t zidx(size_t vb, int z, int y, int x) {
    return vb + (size_t)((y << 3) | (x >> 4)) * 2048 + (z << 4) + (x & 15);
}

__device__ __forceinline__ int brev7(int x) { return (int)(__brev((unsigned)x) >> 25); }
__device__ __forceinline__ int bneg7(int j) {
    int k = brev7(j); k = (VDIM - k) & 127; return brev7(k);
}

__device__ __forceinline__ __half2 pack_h2(float2 v) { return __floats2half2_rn(v.x, v.y); }
__device__ __forceinline__ float2 unpack_h2(__half2 h) { return __half22float2(h); }

// passA/C half2-tile swizzle: 32-bit/32-lane bank-bijective for all phases.
__device__ __forceinline__ int sidxAC(int y, int x) {
    int c = x ^ ((x >> 4) & 7) ^ ((x & 1) << 3)
              ^ (y & 7) ^ ((y >> 4) & 7) ^ ((y & 1) << 3) ^ (y & 8) ^ ((y & 1) << 4);
    return (y << 7) + c;
}
// passB tile swizzle (fp32 tile).
__device__ __forceinline__ int sidxB(int l, int z) {
    int c = z ^ ((z >> 4) & 7) ^ (l & 15);
    return (l << 7) + c;
}

__device__ __forceinline__ float2 cmul(float2 a, float2 w) {
    return make_float2(a.x * w.x - a.y * w.y, a.x * w.y + a.y * w.x);
}
__device__ __forceinline__ float2 cmulc(float2 a, float2 w) {
    return make_float2(a.x * w.x + a.y * w.y, a.y * w.x - a.x * w.y);
}
__device__ __forceinline__ void bf_fwd(float2& ra, float2& rb, float2 w) {
    float2 a = ra, b = rb;
    ra = make_float2(a.x + b.x, a.y + b.y);
    rb = cmul(make_float2(a.x - b.x, a.y - b.y), w);
}
__device__ __forceinline__ void bf_inv(float2& ra, float2& rb, float2 w) {
    float2 a = ra, t = cmulc(rb, w);
    ra = make_float2(a.x + t.x, a.y + t.y);
    rb = make_float2(a.x - t.x, a.y - t.y);
}
__device__ __forceinline__ void bf_triv_fwd(float2& ra, float2& rb) {
    float2 a = ra, b = rb;
    ra = make_float2(a.x + b.x, a.y + b.y);
    rb = make_float2(a.x - b.x, a.y - b.y);
}

// ===== A'/B' split (passA/passC) =====
__device__ __forceinline__ void fftA2_fwd(float2 r[16], int t, const float2* tw) {
    #pragma unroll
    for (int k = 0; k < 8; ++k)
        bf_fwd(r[k], r[k + 8], tw[16 * (k >> 1) + 2 * t + (k & 1)]);
    #pragma unroll
    for (int g = 0; g < 8; ++g) { int k = ((g & ~3) << 1) | (g & 3);
        bf_fwd(r[k], r[k + 4], tw[32 * ((k >> 1) & 1) + 4 * t + 2 * (k & 1)]); }
    #pragma unroll
    for (int g = 0; g < 8; ++g) { int k = ((g & ~1) << 1) | (g & 1);
        bf_fwd(r[k], r[k + 2], tw[8 * t + 4 * (k & 1)]); }
}
__device__ __forceinline__ void fftA2_inv(float2 r[16], int t, const float2* tw) {
    #pragma unroll
    for (int g = 0; g < 8; ++g) { int k = ((g & ~1) << 1) | (g & 1);
        bf_inv(r[k], r[k + 2], tw[8 * t + 4 * (k & 1)]); }
    #pragma unroll
    for (int g = 0; g < 8; ++g) { int k = ((g & ~3) << 1) | (g & 3);
        bf_inv(r[k], r[k + 4], tw[32 * ((k >> 1) & 1) + 4 * t + 2 * (k & 1)]); }
    #pragma unroll
    for (int k = 0; k < 8; ++k)
        bf_inv(r[k], r[k + 8], tw[16 * (k >> 1) + 2 * t + (k & 1)]);
}
__device__ __forceinline__ void fftB2_fwd(float2 r[16], const float2* tw) {
    #pragma unroll
    for (int m = 0; m < 8; ++m) bf_fwd(r[m], r[m + 8], tw[8 * m]);
    #pragma unroll
    for (int g = 0; g < 8; ++g) { int m = ((g & ~3) << 1) | (g & 3);
        bf_fwd(r[m], r[m + 4], tw[16 * (m & 3)]); }
    #pragma unroll
    for (int g = 0; g < 8; ++g) { int m = ((g & ~1) << 1) | (g & 1);
        bf_fwd(r[m], r[m + 2], tw[32 * (m & 1)]); }
    #pragma unroll
    for (int g = 0; g < 8; ++g) bf_triv_fwd(r[2 * g], r[2 * g + 1]);
}
__device__ __forceinline__ void fftB2_inv(float2 r[16], const float2* tw) {
    #pragma unroll
    for (int g = 0; g < 8; ++g) bf_triv_fwd(r[2 * g], r[2 * g + 1]);
    #pragma unroll
    for (int g = 0; g < 8; ++g) { int m = ((g & ~1) << 1) | (g & 1);
        bf_inv(r[m], r[m + 2], tw[32 * (m & 1)]); }
    #pragma unroll
    for (int g = 0; g < 8; ++g) { int m = ((g & ~3) << 1) | (g & 3);
        bf_inv(r[m], r[m + 4], tw[16 * (m & 3)]); }
    #pragma unroll
    for (int m = 0; m < 8; ++m) bf_inv(r[m], r[m + 8], tw[8 * m]);
}

// ===== old A/B split (passB) =====
__device__ __forceinline__ void fftA_fwd(float2 r[16], int t, const float2* tw,
                                         const float2* tw4, const float2* tw8) {
    #pragma unroll
    for (int j = 0; j < 8; ++j) bf_fwd(r[j], r[j + 8], tw[t + 8 * j]);
    #pragma unroll
    for (int g = 0; g < 8; ++g) { int j = ((g & ~3) << 1) | (g & 3); bf_fwd(r[j], r[j + 4], tw[2 * (t + 8 * (j & 3))]); }
    #pragma unroll
    for (int g = 0; g < 8; ++g) { int j = ((g & ~1) << 1) | (g & 1); bf_fwd(r[j], r[j + 2], tw4[t + 8 * (j & 1)]); }
    #pragma unroll
    for (int g = 0; g < 8; ++g) { int j = 2 * g; bf_fwd(r[j], r[j + 1], tw8[t]); }
}
__device__ __forceinline__ void fftA_inv(float2 r[16], int t, const float2* tw,
                                         const float2* tw4, const float2* tw8) {
    #pragma unroll
    for (int g = 0; g < 8; ++g) { int j = 2 * g; bf_inv(r[j], r[j + 1], tw8[t]); }
    #pragma unroll
    for (int g = 0; g < 8; ++g) { int j = ((g & ~1) << 1) | (g & 1); bf_inv(r[j], r[j + 2], tw4[t + 8 * (j & 1)]); }
    #pragma unroll
    for (int g = 0; g < 8; ++g) { int j = ((g & ~3) << 1) | (g & 3); bf_inv(r[j], r[j + 4], tw[2 * (t + 8 * (j & 3))]); }
    #pragma unroll
    for (int j = 0; j < 8; ++j) bf_inv(r[j], r[j + 8], tw[t + 8 * j]);
}
__device__ __forceinline__ void fftB_fwd(float2 r[16], const float2* tw) {
    #pragma unroll
    for (int g = 0; g < 8; ++g) { int m = ((g & ~3) << 1) | (g & 3); bf_fwd(r[m], r[m + 4], tw[(m & 3) << 4]); }
    #pragma unroll
    for (int g = 0; g < 8; ++g) { int m = ((g & ~1) << 1) | (g & 1); bf_fwd(r[m], r[m + 2], tw[(m & 1) << 5]); }
    #pragma unroll
    for (int g = 0; g < 8; ++g) bf_triv_fwd(r[2 * g], r[2 * g + 1]);
}
__device__ __forceinline__ void fftB_inv(float2 r[16], const float2* tw) {
    #pragma unroll
    for (int g = 0; g < 8; ++g) bf_triv_fwd(r[2 * g], r[2 * g + 1]);
    #pragma unroll
    for (int g = 0; g < 8; ++g) { int m = ((g & ~1) << 1) | (g & 1); bf_inv(r[m], r[m + 2], tw[(m & 1) << 5]); }
    #pragma unroll
    for (int g = 0; g < 8; ++g) { int m = ((g & ~3) << 1) | (g & 3); bf_inv(r[m], r[m + 4], tw[(m & 3) << 4]); }
}
__device__ __forceinline__ void init_tw1(float2* tw, int nthr) {
    for (int i = threadIdx.x; i < 64; i += nthr) {
        float sn, cs; sincospif(i * (1.0f / 64.0f), &sn, &cs);
        tw[i] = make_float2(cs, -sn);
    }
}
__device__ __forceinline__ void init_tw3(float2* tw, float2* tw4, float2* tw8, int nthr) {
    for (int i = threadIdx.x; i < 64; i += nthr) {
        float sn, cs; sincospif(i * (1.0f / 64.0f), &sn, &cs);
        float2 w = make_float2(cs, -sn);
        tw[i] = w;
        if (!(i & 3)) tw4[i >> 2] = w;
        if (!(i & 7)) tw8[i >> 3] = w;
    }
}

// Pass A: pack v1 + i*v2, forward FFT along x then y per (b,z) slab.
__global__ __launch_bounds__(256, 2) void passA(const float* __restrict__ v1,
                                                const float* __restrict__ v2) {
    extern __shared__ char raw[];
    __half2* tile = (__half2*)raw;                     // 128*128 half2 = 65,536 B
    float2* tw = (float2*)(raw + 65536);
    init_tw1(tw, 256);
    const int tid = threadIdx.x, w2 = tid >> 5, lane = tid & 31;
    const int t = lane & 7, q = (lane >> 3) & 1, h = lane >> 4;
    const int z = blockIdx.x & 127;
    const size_t vb = (size_t)(blockIdx.x >> 7) * VOL;
    const size_t base = (size_t)blockIdx.x * SLAB;     // input layout (b,z,y,x)
    float2 r[16];
    __syncthreads();
    #pragma unroll 1
    for (int it = 0; it < 4; ++it) {                   // x-dim, pattern A' (float2 gmem in)
        const int y = 2 * w2 + 32 * (it >> 1) + 16 * q + h + 64 * (it & 1);
        const float* p1 = v1 + base + y * VDIM + 2 * t;
        const float* p2 = v2 + base + y * VDIM + 2 * t;
        #pragma unroll
        for (int j = 0; j < 8; ++j) {
            const float2 a = *(const float2*)(p1 + 16 * j);
            const float2 b = *(const float2*)(p2 + 16 * j);
            r[2 * j]     = make_float2(a.x, b.x);
            r[2 * j + 1] = make_float2(a.y, b.y);
        }
        fftA2_fwd(r, t, tw);
        #pragma unroll
        for (int k = 0; k < 16; ++k)
            tile[sidxAC(y, 16 * (k >> 1) + 2 * t + (k & 1))] = pack_h2(r[k]);
    }
    __syncwarp();
    #pragma unroll 1
    for (int it = 0; it < 4; ++it) {                   // x-dim, pattern B'
        const int y = 2 * w2 + 32 * (it >> 1) + q + 16 * h + 64 * (it & 1);
        #pragma unroll
        for (int m = 0; m < 16; ++m) r[m] = unpack_h2(tile[sidxAC(y, 16 * t + m)]);
        fftB2_fwd(r, tw);
        #pragma unroll
        for (int m = 0; m < 16; ++m) tile[sidxAC(y, 16 * t + m)] = pack_h2(r[m]);
    }
    __syncthreads();
    #pragma unroll 1
    for (int it = 0; it < 4; ++it) {                   // y-dim, pattern A'
        const int x = 2 * w2 + 32 * (it >> 1) + 16 * q + h + 64 * (it & 1);
        #pragma unroll
        for (int k = 0; k < 16; ++k)
            r[k] = unpack_h2(tile[sidxAC(16 * (k >> 1) + 2 * t + (k & 1), x)]);
        fftA2_fwd(r, t, tw);
        #pragma unroll
        for (int k = 0; k < 16; ++k)
            tile[sidxAC(16 * (k >> 1) + 2 * t + (k & 1), x)] = pack_h2(r[k]);
    }
    __syncthreads();
    #pragma unroll 1
    for (int it = 0; it < 4; ++it) {                   // y-dim, pattern B' (g_Z out, tiled layout)
        const int x = lane + 32 * (it >> 1) + 64 * (it & 1);
        #pragma unroll
        for (int m = 0; m < 16; ++m) r[m] = unpack_h2(tile[sidxAC(16 * w2 + m, x)]);
        fftB2_fwd(r, tw);
        #pragma unroll
        for (int m = 0; m < 16; ++m)
            g_Z[zidx(vb, z, 16 * w2 + m, x)] = pack_h2(r[m]);
    }
}

__device__ __forceinline__ float2 Hval(float2 Z, float2 Zn) {
    const float px = Z.x + Zn.x, py = Z.y - Zn.y;   // 2*F1
    const float qx = Z.x - Zn.x, qy = Z.y + Zn.y;   // 2i*F2
    return make_float2(0.25f * (px * qy - py * qx),
                       0.25f * (px * qx + py * qy));
}

// Pass B: z-FFT + pointwise + inverse z-FFT; g_Z tiled layout makes z-columns stream.
__global__ __launch_bounds__(256, 2) void passB() {
    extern __shared__ char raw[];
    float2* tile = (float2*)raw;                    // 64 lines x 128 (z)
    float2* tw = tile + 64 * 128; float2* tw4 = tw + 64; float2* tw8 = tw4 + 16;
    const int xt = blockIdx.x, jy = blockIdx.y, b = blockIdx.z;
    const int jy2 = bneg7(jy);
    const int xt2 = (xt < 2) ? xt : (5 - xt);
    if (jy2 < jy || (jy2 == jy && xt2 < xt)) return;
    const bool full = (jy2 == jy);
    init_tw3(tw, tw4, tw8, 256);
    const int tid = threadIdx.x;
    const int t = (tid >> 4) & 7;
    const int l0 = ((tid >> 7) << 4) | (tid & 15);
    const int l1 = l0 + 32;
    const size_t vb = (size_t)b * VOL;
    const size_t gb0 = zidx(vb, 0, jy,  32 * xt  + l0);
    const size_t gb1 = zidx(vb, 0, jy2, 32 * xt2 + l0);
    const float SCL = 1.0f / (float)VOL;
    float2 r[16];
    __syncthreads();
    #pragma unroll
    for (int j = 0; j < 16; ++j) r[j] = unpack_h2(g_Z[gb0 + ((t + 8 * j) << 4)]);
    fftA_fwd(r, t, tw, tw4, tw8);
    #pragma unroll
    for (int j = 0; j < 16; ++j) tile[sidxB(l0, t + 8 * j)] = r[j];
    #pragma unroll
    for (int j = 0; j < 16; ++j) r[j] = unpack_h2(g_Z[gb1 + ((t + 8 * j) << 4)]);
    fftA_fwd(r, t, tw, tw4, tw8);
    #pragma unroll
    for (int j = 0; j < 16; ++j) tile[sidxB(l1, t + 8 * j)] = r[j];
    __syncthreads();
    #pragma unroll
    for (int m = 0; m < 16; ++m) r[m] = tile[sidxB(l0, 16 * t + m)];
    fftB_fwd(r, tw);
    #pragma unroll
    for (int m = 0; m < 16; ++m) tile[sidxB(l0, 16 * t + m)] = r[m];
    #pragma unroll
    for (int m = 0; m < 16; ++m) r[m] = tile[sidxB(l1, 16 * t + m)];
    fftB_fwd(r, tw);
    #pragma unroll
    for (int m = 0; m < 16; ++m) tile[sidxB(l1, 16 * t + m)] = r[m];
    __syncthreads();
    #pragma unroll 1
    for (int i = tid; i < 32 * 128; i += 256) {
        const int jz = i & 127, row = i >> 7;
        const int jzn = bneg7(jz);
        if (jzn < jz) continue;
        const int pr = 32 + bneg7(32 * xt + row) - 32 * xt2;
        const float2 a1 = tile[sidxB(row, jz)], a2 = tile[sidxB(row, jzn)];
        const float2 b1 = tile[sidxB(pr, jz)],  b2 = tile[sidxB(pr, jzn)];
        tile[sidxB(row, jz)]  = Hval(a1, b2);
        tile[sidxB(pr, jz)]   = Hval(b1, a2);
        tile[sidxB(row, jzn)] = Hval(a2, b1);
        tile[sidxB(pr, jzn)]  = Hval(b2, a1);
    }
    __syncthreads();
    #pragma unroll
    for (int m = 0; m < 16; ++m) r[m] = tile[sidxB(l0, 16 * t + m)];
    fftB_inv(r, tw);
    #pragma unroll
    for (int m = 0; m < 16; ++m) tile[sidxB(l0, 16 * t + m)] = r[m];
    if (full) {
        #pragma unroll
        for (int m = 0; m < 16; ++m) r[m] = tile[sidxB(l1, 16 * t + m)];
        fftB_inv(r, tw);
        #pragma unroll
        for (int m = 0; m < 16; ++m) tile[sidxB(l1, 16 * t + m)] = r[m];
    }
    __syncthreads();
    #pragma unroll
    for (int j = 0; j < 16; ++j) r[j] = tile[sidxB(l0, t + 8 * j)];
    fftA_inv(r, t, tw, tw4, tw8);
    #pragma unroll
    for (int j = 0; j < 16; ++j)
        g_Z[gb0 + ((t + 8 * j) << 4)] =
            pack_h2(make_float2(r[j].x * SCL, r[j].y * SCL));
    if (full) {
        #pragma unroll
        for (int j = 0; j < 16; ++j) r[j] = tile[sidxB(l1, t + 8 * j)];
        fftA_inv(r, t, tw, tw4, tw8);
        #pragma unroll
        for (int j = 0; j < 16; ++j)
            g_Z[gb1 + ((t + 8 * j) << 4)] =
                pack_h2(make_float2(r[j].x * SCL, r[j].y * SCL));
    }
}

// Pass C: gather half-spectrum + mirror conj fill, inverse y then x FFTs, float2 out.
__global__ __launch_bounds__(256, 2) void passC(float* __restrict__ out) {
    extern __shared__ char raw[];
    __half2* tile = (__half2*)raw;
    float2* tw = (float2*)(raw + 65536);
    init_tw1(tw, 256);
    const int tid = threadIdx.x, w2 = tid >> 5, lane = tid & 31;
    const int t = lane & 7, q = (lane >> 3) & 1, h = lane >> 4;
    const int z = blockIdx.x & 127;
    const size_t vb = (size_t)(blockIdx.x >> 7) * VOL;
    const size_t base = (size_t)blockIdx.x * SLAB;      // output layout (b,z,y,x)
    float2 r[16];
    __syncthreads();
    // gather copy-in: load kept rows (jy <= bneg7(jy)); mirror-fill conj rows.
    #pragma unroll 1
    for (int jy = w2; jy < 128; jy += 8) {
        const int jy2 = bneg7(jy);
        if (jy > jy2) continue;
        #pragma unroll
        for (int k = 0; k < 4; ++k) {
            const int xx = lane + 32 * k;
            __half2 v = g_Z[zidx(vb, z, jy, xx)];
            tile[sidxAC(jy, xx)] = v;
            if (jy2 != jy) {
                __half2 c = v; c.y = __hneg(c.y);
                tile[sidxAC(jy2, bneg7(xx))] = c;
            }
        }
    }
    __syncthreads();
    #pragma unroll 1
    for (int it = 0; it < 4; ++it) {                   // y-dim, pattern B' (from smem)
        const int x = lane + 32 * (it >> 1) + 64 * (it & 1);
        #pragma unroll
        for (int m = 0; m < 16; ++m) r[m] = unpack_h2(tile[sidxAC(16 * w2 + m, x)]);
        fftB2_inv(r, tw);
        #pragma unroll
        for (int m = 0; m < 16; ++m) tile[sidxAC(16 * w2 + m, x)] = pack_h2(r[m]);
    }
    __syncthreads();
    #pragma unroll 1
    for (int it = 0; it < 4; ++it) {                   // y-dim, pattern A'
        const int x = 2 * w2 + 32 * (it >> 1) + 16 * q + h + 64 * (it & 1);
        #pragma unroll
        for (int k = 0; k < 16; ++k)
            r[k] = unpack_h2(tile[sidxAC(16 * (k >> 1) + 2 * t + (k & 1), x)]);
        fftA2_inv(r, t, tw);
        #pragma unroll
        for (int k = 0; k < 16; ++k)
            tile[sidxAC(16 * (k >> 1) + 2 * t + (k & 1), x)] = pack_h2(r[k]);
    }
    __syncthreads();
    #pragma unroll 1
    for (int it = 0; it < 4; ++it) {                   // x-dim, pattern B'
        const int y = 2 * w2 + 32 * (it >> 1) + q + 16 * h + 64 * (it & 1);
        #pragma unroll
        for (int m = 0; m < 16; ++m) r[m] = unpack_h2(tile[sidxAC(y, 16 * t + m)]);
        fftB2_inv(r, tw);
        #pragma unroll
        for (int m = 0; m < 16; ++m) tile[sidxAC(y, 16 * t + m)] = pack_h2(r[m]);
    }
    __syncwarp();
    #pragma unroll 1
    for (int it = 0; it < 4; ++it) {                   // x-dim, pattern A' -> float2 out
        const int y = 2 * w2 + 32 * (it >> 1) + 16 * q + h + 64 * (it & 1);
        #pragma unroll
        for (int k = 0; k < 16; ++k)
            r[k] = unpack_h2(tile[sidxAC(y, 16 * (k >> 1) + 2 * t + (k & 1))]);
        fftA2_inv(r, t, tw);
        float* po = out + base + y * VDIM + 2 * t;
        #pragma unroll
        for (int j = 0; j < 8; ++j)
            *(float2*)(po + 16 * j) = make_float2(r[2 * j].x, r[2 * j + 1].x);
    }
}

extern "C" void kernel_launch(void* const* d_in, const int* in_sizes, int n_in,
                              void* d_out, int out_size) {
    const float* v1 = (const float*)d_in[0];
    const float* v2 = (const float*)d_in[1];
    float* out = (float*)d_out;
    const int smAC = 65536 + 64 * (int)sizeof(float2);                 // 66,048 B
    const int smB  = (64 * 128 + 64 + 16 + 8) * (int)sizeof(float2);   // 66,240 B
    cudaFuncSetAttribute(passA, cudaFuncAttributeMaxDynamicSharedMemorySize, smAC);
    cudaFuncSetAttribute(passC, cudaFuncAttributeMaxDynamicSharedMemorySize, smAC);
    cudaFuncSetAttribute(passB, cudaFuncAttributeMaxDynamicSharedMemorySize, smB);
    passA<<<NB * VDIM, 256, smAC>>>(v1, v2);
    passB<<<dim3(4, VDIM, NB), 256, smB>>>();
    passC<<<NB * VDIM, 256, smAC>>>(out);
}